// round 11
// baseline (speedup 1.0000x reference)
#include <cuda_runtime.h>
#include <cstdint>

#define FULL_MASK 0xFFFFFFFFu
#define NQ 8
#define DEPTH 3
#define FDIM 512
#define NCLS 10
#define BTHREADS 128
#define MAXB 8192

typedef unsigned long long u64;

// ---- device-global scratch (allocation-free) ----
__device__ float2 g_cs[MAXB * NQ];      // (cos, sin) of half-angle per (b, q)
__device__ float4 g_gates[DEPTH * NQ][2];

// ---- packed f32x2 helpers (proj kernel reduce only) ----
__device__ __forceinline__ u64 pk2(float lo, float hi) {
    u64 r; asm("mov.b64 %0,{%1,%2};" : "=l"(r) : "f"(lo), "f"(hi)); return r;
}
__device__ __forceinline__ void up2(u64 v, float& lo, float& hi) {
    asm("mov.b64 {%0,%1},%2;" : "=f"(lo), "=f"(hi) : "l"(v));
}
__device__ __forceinline__ u64 add2_(u64 a, u64 b) {
    u64 d; asm("add.rn.f32x2 %0,%1,%2;" : "=l"(d) : "l"(a), "l"(b)); return d;
}

// ============================================================
// Kernel 1: projection + tanh + half-angle sincos -> g_cs ; gates -> g_gates
// (unchanged from R10 - proven)
// ============================================================
__global__ void __launch_bounds__(BTHREADS, 8) proj_kernel(
    const float* __restrict__ x,       // (B, 512)
    const float* __restrict__ proj_w,  // (8, 512)
    const float* __restrict__ qnn_w,   // (72,)
    int B)
{
    const int tid  = threadIdx.x;
    const int lane = tid & 31;
    const int warp = tid >> 5;

    if (blockIdx.x == 0 && tid < DEPTH * NQ) {
        float w0 = qnn_w[tid * 3 + 0];
        float w1 = qnn_w[tid * 3 + 1];
        float w2 = qnn_w[tid * 3 + 2];
        float c0, s0, c1, s1, c2, s2;
        sincosf(0.5f * w0, &s0, &c0);
        sincosf(0.5f * w1, &s1, &c1);
        sincosf(0.5f * w2, &s2, &c2);
        float2 A00 = { c1 * c0,  s1 * s0};
        float2 A01 = {-s1 * c0, -c1 * s0};
        float2 A10 = { s1 * c0, -c1 * s0};
        float2 A11 = { c1 * c0, -s1 * s0};
        float2 q00 = make_float2(c2 * A00.x + s2 * A10.y, c2 * A00.y - s2 * A10.x);
        float2 q01 = make_float2(c2 * A01.x + s2 * A11.y, c2 * A01.y - s2 * A11.x);
        float2 q10 = make_float2(c2 * A10.x + s2 * A00.y, c2 * A10.y - s2 * A00.x);
        float2 q11 = make_float2(c2 * A11.x + s2 * A01.y, c2 * A11.y - s2 * A01.x);
        g_gates[tid][0] = make_float4(q00.x, q00.y, q01.x, q01.y);
        g_gates[tid][1] = make_float4(q10.x, q10.y, q11.x, q11.y);
    }

    const int b0 = (blockIdx.x * 4 + warp) * 2;
    const int b1 = b0 + 1;
    if (b0 >= B) return;
    const bool v1 = (b1 < B);

    float acc[2][NQ];
    #pragma unroll
    for (int e = 0; e < 2; e++)
        #pragma unroll
        for (int q = 0; q < NQ; q++) acc[e][q] = 0.f;

    const float4* xr0 = (const float4*)(x + (size_t)b0 * FDIM);
    const float4* xr1 = (const float4*)(x + (size_t)(v1 ? b1 : b0) * FDIM);
    #pragma unroll
    for (int ch = 0; ch < 4; ch++) {
        float4 xv0 = xr0[ch * 32 + lane];
        float4 xv1 = xr1[ch * 32 + lane];
        #pragma unroll
        for (int q = 0; q < NQ; q++) {
            float4 wv = __ldg((const float4*)&proj_w[q * FDIM + ch * 128 + lane * 4]);
            acc[0][q] += xv0.x*wv.x + xv0.y*wv.y + xv0.z*wv.z + xv0.w*wv.w;
            acc[1][q] += xv1.x*wv.x + xv1.y*wv.y + xv1.z*wv.z + xv1.w*wv.w;
        }
    }
    auto mrgP = [&](u64 a, u64 b, int dist) -> u64 {
        u64 c = (lane & dist) ? b : a;
        u64 d = (lane & dist) ? a : b;
        return add2_(c, __shfl_xor_sync(FULL_MASK, d, dist));
    };
    u64 ap[8];
    #pragma unroll
    for (int q = 0; q < NQ; q++) ap[q] = pk2(acc[0][q], acc[1][q]);
    u64 m0 = mrgP(ap[0], ap[1], 16), m1 = mrgP(ap[2], ap[3], 16);
    u64 m2 = mrgP(ap[4], ap[5], 16), m3 = mrgP(ap[6], ap[7], 16);
    u64 n0 = mrgP(m0, m1, 8), n1 = mrgP(m2, m3, 8);
    u64 F  = mrgP(n0, n1, 4);
    F = add2_(F, __shfl_xor_sync(FULL_MASK, F, 2));
    F = add2_(F, __shfl_xor_sync(FULL_MASK, F, 1));

    if ((lane & 3) == 0) {
        const int q = ((lane >> 4) & 1) | (((lane >> 3) & 1) << 1) | (((lane >> 2) & 1) << 2);
        float dA, dB; up2(F, dA, dB);
        float hA = tanhf(dA) * 0.78539816339744830962f;
        float hB = tanhf(dB) * 0.78539816339744830962f;
        float cA, sA, cB, sB;
        __sincosf(hA, &sA, &cA);
        __sincosf(hB, &sB, &cB);
        g_cs[b0 * NQ + q] = make_float2(cA, sA);
        if (v1) g_cs[b1 * NQ + q] = make_float2(cB, sB);
    }
}

// ============================================================
// Kernel 2: circuit — 1 element per warp, scalar (R3-proven gate code)
// ============================================================
// Deferred-CNOT masks (GF(2)); layout p = (lane<<3)|r.
// parity table for 3-bit values: 0x96
template<int PM, int W>
__device__ __forceinline__ void gate_apply(float ar[8], float ai[8],
                                           float4 A, float4 Bv, int lane)
{
    constexpr int pr = PM & 7;
    constexpr int pl = PM >> 3;
    constexpr int wr = W & 7;
    constexpr int wl = W >> 3;
    const float2 u00 = make_float2(A.x, A.y),  u01 = make_float2(A.z, A.w);
    const float2 u10 = make_float2(Bv.x, Bv.y), u11 = make_float2(Bv.z, Bv.w);
    bool bL = (wl != 0) && ((__popc(lane & wl) & 1) != 0);
    float2 oA = bL ? u11 : u00, pA = bL ? u10 : u01;
    float2 oB = bL ? u00 : u11, pB = bL ? u01 : u10;

    if constexpr (pl == 0) {
        #pragma unroll
        for (int r = 0; r < 8; r++) {
            if (((0x96 >> (r & wr)) & 1) == 0) {   // base of pair (compile-time)
                const int r1 = r ^ pr;
                float a0r = ar[r],  a0i = ai[r];
                float a1r = ar[r1], a1i = ai[r1];
                ar[r]  = oA.x * a0r - oA.y * a0i + pA.x * a1r - pA.y * a1i;
                ai[r]  = oA.x * a0i + oA.y * a0r + pA.x * a1i + pA.y * a1r;
                ar[r1] = oB.x * a1r - oB.y * a1i + pB.x * a0r - pB.y * a0i;
                ai[r1] = oB.x * a1i + oB.y * a1r + pB.x * a0i + pB.y * a0r;
            }
        }
    } else if constexpr (pr == 0) {
        #pragma unroll
        for (int r = 0; r < 8; r++) {
            float tr = __shfl_xor_sync(FULL_MASK, ar[r], pl);
            float ti = __shfl_xor_sync(FULL_MASK, ai[r], pl);
            const bool pb = ((0x96 >> (r & wr)) & 1) != 0;   // compile-time
            float2 o = pb ? oB : oA;
            float2 p = pb ? pB : pA;
            float nr = o.x*ar[r] - o.y*ai[r] + p.x*tr - p.y*ti;
            float ni = o.x*ai[r] + o.y*ar[r] + p.x*ti + p.y*tr;
            ar[r] = nr; ai[r] = ni;
        }
    } else {
        #pragma unroll
        for (int r = 0; r < 8; r++) {
            if (r < (r ^ pr)) {                       // compile-time pair rep
                const int r1 = r ^ pr;
                float sr0 = __shfl_xor_sync(FULL_MASK, ar[r1], pl);
                float si0 = __shfl_xor_sync(FULL_MASK, ai[r1], pl);
                float sr1 = __shfl_xor_sync(FULL_MASK, ar[r],  pl);
                float si1 = __shfl_xor_sync(FULL_MASK, ai[r],  pl);
                const bool pb0 = ((0x96 >> (r  & wr)) & 1) != 0;
                const bool pb1 = ((0x96 >> (r1 & wr)) & 1) != 0;
                float2 o0 = pb0 ? oB : oA, p0 = pb0 ? pB : pA;
                float2 o1 = pb1 ? oB : oA, p1 = pb1 ? pB : pA;
                float nr0 = o0.x*ar[r]  - o0.y*ai[r]  + p0.x*sr0 - p0.y*si0;
                float ni0 = o0.x*ai[r]  + o0.y*ar[r]  + p0.x*si0 + p0.y*sr0;
                float nr1 = o1.x*ar[r1] - o1.y*ai[r1] + p1.x*sr1 - p1.y*si1;
                float ni1 = o1.x*ai[r1] + o1.y*ar[r1] + p1.x*si1 + p1.y*sr1;
                ar[r]  = nr0; ai[r]  = ni0;
                ar[r1] = nr1; ai[r1] = ni1;
            }
        }
    }
}

__global__ void __launch_bounds__(BTHREADS, 10) circuit_kernel(
    const float* __restrict__ out_w,   // (10, 8)
    const float* __restrict__ out_b,   // (10,)
    float* __restrict__ out,           // (B, 10)
    int B)
{
    __shared__ float4 s_g4[DEPTH * NQ][2];   // 768 B
    __shared__ float  s_ow[NCLS * NQ];
    __shared__ float  s_ob[NCLS];

    const int tid  = threadIdx.x;
    const int lane = tid & 31;
    const int warp = tid >> 5;

    if (tid < DEPTH * NQ * 2) ((float4*)s_g4)[tid] = ((const float4*)g_gates)[tid];
    if (tid < NCLS * NQ) s_ow[tid] = out_w[tid];
    if (tid < NCLS)      s_ob[tid] = out_b[tid];
    __syncthreads();

    auto mrg = [&](float a, float b, int dist) {
        float c = (lane & dist) ? b : a;
        float d = (lane & dist) ? a : b;
        return c + __shfl_xor_sync(FULL_MASK, d, dist);
    };
    auto srcLane = [](int q) { return ((q & 1) << 4) | (((q >> 1) & 1) << 3) | (((q >> 2) & 1) << 2); };

    const int b = blockIdx.x * 4 + warp;   // one element per warp
    if (b >= B) return;

    // half-angle cos/sin: lane q (q<8) holds qubit q's pair
    float2 t = __ldg(&g_cs[b * NQ + (lane & 7)]);

    // ---- product state (encoding + layer-0 gates), scalar ----
    float Lr = 1.f, Li = 0.f;
    #pragma unroll
    for (int k = 0; k < 5; k++) {
        const int q = k + 3;
        float c = __shfl_sync(FULL_MASK, t.x, q);
        float s = __shfl_sync(FULL_MASK, t.y, q);
        float4 V = s_g4[q][(lane >> k) & 1];
        float wx = V.x * c + V.z * s;
        float wy = V.y * c + V.w * s;
        float nr = Lr * wx - Li * wy;
        float ni = Lr * wy + Li * wx;
        Lr = nr; Li = ni;
    }
    float ar[8], ai[8];
    {
        float c = __shfl_sync(FULL_MASK, t.x, 0);
        float s = __shfl_sync(FULL_MASK, t.y, 0);
        float4 A0 = s_g4[0][0], B0 = s_g4[0][1];
        float a0x = A0.x*c + A0.z*s, a0y = A0.y*c + A0.w*s;
        float b0x = B0.x*c + B0.z*s, b0y = B0.y*c + B0.w*s;
        ar[0] = Lr*a0x - Li*a0y;  ai[0] = Lr*a0y + Li*a0x;
        ar[1] = Lr*b0x - Li*b0y;  ai[1] = Lr*b0y + Li*b0x;
    }
    {
        float c = __shfl_sync(FULL_MASK, t.x, 1);
        float s = __shfl_sync(FULL_MASK, t.y, 1);
        float4 A1 = s_g4[1][0], B1 = s_g4[1][1];
        float a1x = A1.x*c + A1.z*s, a1y = A1.y*c + A1.w*s;
        float b1x = B1.x*c + B1.z*s, b1y = B1.y*c + B1.w*s;
        #pragma unroll
        for (int r = 0; r < 2; r++) {
            float tr = ar[r], ti = ai[r];
            ar[r + 2] = tr*b1x - ti*b1y;  ai[r + 2] = tr*b1y + ti*b1x;
            ar[r]     = tr*a1x - ti*a1y;  ai[r]     = tr*a1y + ti*a1x;
        }
    }
    {
        float c = __shfl_sync(FULL_MASK, t.x, 2);
        float s = __shfl_sync(FULL_MASK, t.y, 2);
        float4 A2 = s_g4[2][0], B2 = s_g4[2][1];
        float a2x = A2.x*c + A2.z*s, a2y = A2.y*c + A2.w*s;
        float b2x = B2.x*c + B2.z*s, b2y = B2.y*c + B2.w*s;
        #pragma unroll
        for (int r = 0; r < 4; r++) {
            float tr = ar[r], ti = ai[r];
            ar[r + 4] = tr*b2x - ti*b2y;  ai[r + 4] = tr*b2y + ti*b2x;
            ar[r]     = tr*a2x - ti*a2y;  ai[r]     = tr*a2y + ti*a2x;
        }
    }

    // ---- layers 1,2 with deferred-CNOT masks ----
    #define GATE(idx, PMv, Wv) gate_apply<PMv, Wv>(ar, ai, s_g4[idx][0], s_g4[idx][1], lane)
    // layer 1 (phi = C)
    GATE(8,  0x03, 0xFE); GATE(9,  0x06, 0x03); GATE(10, 0x0C, 0x07); GATE(11, 0x18, 0x0F);
    GATE(12, 0x30, 0x1F); GATE(13, 0x60, 0x3F); GATE(14, 0xC0, 0x7F); GATE(15, 0x83, 0xFF);
    // layer 2 (phi = C^2)
    GATE(16, 0x05, 0xAB); GATE(17, 0x0A, 0xFD); GATE(18, 0x14, 0xFA); GATE(19, 0x28, 0xF5);
    GATE(20, 0x50, 0xEA); GATE(21, 0xA0, 0xD5); GATE(22, 0x43, 0xAA); GATE(23, 0x86, 0x55);
    #undef GATE

    // ---- PauliZ via Walsh-Hadamard of |amp|^2 (phi = C^3) ----
    float S[8];
    #pragma unroll
    for (int r = 0; r < 8; r++) S[r] = ar[r]*ar[r] + ai[r]*ai[r];
    #pragma unroll
    for (int st = 0; st < 3; st++) {
        const int d = 1 << st;
        #pragma unroll
        for (int r = 0; r < 8; r++) {
            if (!(r & d)) {
                float a = S[r] + S[r + d];
                float bm = S[r] - S[r + d];
                S[r] = a; S[r + d] = bm;
            }
        }
    }
    auto sg = [&](int wl, float v) { return (__popc(lane & wl) & 1) ? -v : v; };
    float z0 = sg(0x06, S[2]), z1 = sg(0x0A, S[6]);
    float z2 = sg(0x15, S[4]), z3 = sg(0x0B, S[1]);
    float z4 = sg(0x16, S[3]), z5 = sg(0x0C, S[6]);
    float z6 = sg(0x19, S[4]), z7 = sg(0x13, S[1]);
    float m0 = mrg(z0, z1, 16), m1 = mrg(z2, z3, 16);
    float m2 = mrg(z4, z5, 16), m3 = mrg(z6, z7, 16);
    float n0 = mrg(m0, m1, 8),  n1 = mrg(m2, m3, 8);
    float f  = mrg(n0, n1, 4);
    f += __shfl_xor_sync(FULL_MASK, f, 2);
    f += __shfl_xor_sync(FULL_MASK, f, 1);
    float g[NQ];
    #pragma unroll
    for (int q = 0; q < NQ; q++) g[q] = __shfl_sync(FULL_MASK, f, srcLane(q));

    // ---- output head ----
    if (lane < NCLS) {
        float o = s_ob[lane];
        #pragma unroll
        for (int q = 0; q < NQ; q++) o += g[q] * s_ow[lane * NQ + q];
        out[(size_t)b * NCLS + lane] = o;
    }
}

extern "C" void kernel_launch(void* const* d_in, const int* in_sizes, int n_in,
                              void* d_out, int out_size) {
    const float* x      = (const float*)d_in[0];
    const float* proj_w = (const float*)d_in[1];
    const float* qnn_w  = (const float*)d_in[2];
    const float* out_w  = (const float*)d_in[3];
    const float* out_b  = (const float*)d_in[4];
    float* out = (float*)d_out;

    int B = in_sizes[0] / FDIM;              // 8192
    int pblocks = (B + 7) / 8;               // 1024: proj, 2 elems/warp
    int cblocks = (B + 3) / 4;               // 2048: circuit, 1 elem/warp
    proj_kernel<<<pblocks, BTHREADS>>>(x, proj_w, qnn_w, B);
    circuit_kernel<<<cblocks, BTHREADS>>>(out_w, out_b, out, B);
}